// round 14
// baseline (speedup 1.0000x reference)
#include <cuda_runtime.h>

#define NN 100000
#define F  64
#define CAP 64                                 // slots per node (P(deg>=64) ~ 1e-20)
#define NCH3 ((NN + 127) / 128)                // 782 chunks of 128 nodes

typedef unsigned long long ull;

// Scratch (allocation-free: __device__ globals)
__device__ __align__(16) float g_agg[(size_t)NN * F];
__device__ __align__(16) float g_x2[(size_t)NN * F];
__device__ int g_deg[NN];
__device__ __align__(16) int g_slot[(size_t)NN * CAP];   // 25.6 MB bucket rows

__device__ __forceinline__ ull ffma2(ull a, ull b, ull c) {
    ull d;
    asm("fma.rn.f32x2 %0, %1, %2, %3;" : "=l"(d) : "l"(a), "l"(b), "l"(c));
    return d;
}
__device__ __forceinline__ ull dup2(float x) {
    ull d;
    asm("mov.b64 %0, {%1, %1};" : "=l"(d) : "f"(x));
    return d;
}
__device__ __forceinline__ ull pack2(float lo, float hi) {
    ull d;
    asm("mov.b64 %0, {%1, %2};" : "=l"(d) : "f"(lo), "f"(hi));
    return d;
}
__device__ __forceinline__ float2 unpack2(ull v) {
    float2 r;
    asm("mov.b64 {%0, %1}, %2;" : "=f"(r.x), "=f"(r.y) : "l"(v));
    return r;
}

__global__ void zero_deg_kernel() {
    int i = blockIdx.x * blockDim.x + threadIdx.x;
    if (i < NN) g_deg[i] = 0;
}

// Single-pass bucket fill: the fill IS the histogram.
__global__ void fill_kernel(const int* __restrict__ src,
                            const int* __restrict__ dst, int E) {
    int e = blockIdx.x * blockDim.x + threadIdx.x;
    if (e >= E) return;
    int d = __ldg(&dst[e]);
    int s = __ldg(&src[e]);
    if ((unsigned)d >= NN || (unsigned)s >= NN) return;
    int pos = atomicAdd(&g_deg[d], 1);
    if (pos < CAP) g_slot[(size_t)d * CAP + pos] = s;
}

// Bucket mean aggregation: 16 threads/node, float4 slices, int4 index loads.
__global__ void agg_kernel(const float4* __restrict__ x4,
                           float4* __restrict__ out4) {
    int t = blockIdx.x * blockDim.x + threadIdx.x;
    int node = t >> 4;
    int sub = t & 15;
    if (node >= NN) return;
    int degt = g_deg[node];
    int deg = min(degt, CAP);
    const int4* idx4 = reinterpret_cast<const int4*>(&g_slot[(size_t)node * CAP]);
    float4 a = make_float4(0.f, 0.f, 0.f, 0.f);
    float4 b = make_float4(0.f, 0.f, 0.f, 0.f);
    int i = 0;
    for (; i + 4 <= deg; i += 4) {
        int4 q = __ldg(&idx4[i >> 2]);
        float4 v0 = __ldg(&x4[(size_t)q.x * 16 + sub]);
        float4 v1 = __ldg(&x4[(size_t)q.y * 16 + sub]);
        float4 v2 = __ldg(&x4[(size_t)q.z * 16 + sub]);
        float4 v3 = __ldg(&x4[(size_t)q.w * 16 + sub]);
        a.x += v0.x + v1.x; a.y += v0.y + v1.y;
        a.z += v0.z + v1.z; a.w += v0.w + v1.w;
        b.x += v2.x + v3.x; b.y += v2.y + v3.y;
        b.z += v2.z + v3.z; b.w += v2.w + v3.w;
    }
    for (; i < deg; i++) {
        int s0 = g_slot[(size_t)node * CAP + i];
        float4 v0 = __ldg(&x4[(size_t)s0 * 16 + sub]);
        a.x += v0.x; a.y += v0.y; a.z += v0.z; a.w += v0.w;
    }
    float inv = 1.0f / (float)max(degt, 1);
    out4[(size_t)node * 16 + sub] =
        make_float4((a.x + b.x) * inv, (a.y + b.y) * inv,
                    (a.z + b.z) * inv, (a.w + b.w) * inv);
}

// Fused layer, f32x2 FMA, 2 features (j, j+32) x 8 node-pairs per thread.
// Weights stored TRANSPOSED in smem ([j][k]) -> float4 loads over k.
// Chunk = 128 nodes. smem: 48KB weights + 32KB M (reused for T) + 32KB H.
template <bool RELU2>
__global__ void __launch_bounds__(256, 2)
fused_layer(const float* __restrict__ xin,
            const float* __restrict__ Wl,
            const float* __restrict__ bl,
            const float* __restrict__ Wr,
            const float* __restrict__ W2,
            const float* __restrict__ b2,
            float* __restrict__ out) {
    extern __shared__ char smraw[];
    float* sWlT = (float*)smraw;           // 16KB  [j][k]
    float* sWrT = sWlT + F * F;            // 16KB
    float* sW2T = sWrT + F * F;            // 16KB
    ull* sMp = (ull*)(sW2T + F * F);       // 64 pairs x 64 = 32KB (reused for T)
    ull* sHp = sMp + 64 * F;               // 32KB   (total 112KB)

    int j = threadIdx.x;                   // 0..31
    int g = threadIdx.y;                   // 0..7
    int jB = j + 32;
    int tid = g * 32 + j;
    // Transposed weight fill: sWT[jj*F + k] = W[k*F + jj]
    for (int i = tid; i < F * F; i += 256) {
        int jj = i >> 6, k = i & 63;
        sWlT[i] = Wl[k * F + jj];
        sWrT[i] = Wr[k * F + jj];
        sW2T[i] = W2[k * F + jj];
    }
    float blA = bl[j],  blB = bl[jB];
    float b2A = b2[j],  b2B = b2[jB];

    const ulonglong2* mp2 = (const ulonglong2*)sMp;
    const ulonglong2* hp2 = (const ulonglong2*)sHp;

    for (int chunk = blockIdx.x; chunk < NCH3; chunk += gridDim.x) {
        __syncthreads();
        int base16 = chunk * 128 + g * 16;
        // Stage 8 pairs per group, both feature halves (clamped for tail)
        #pragma unroll
        for (int q = 0; q < 8; q++) {
            int n0 = base16 + 2 * q;
            int n0c = min(n0, NN - 2);
            int pr = g * 8 + q;
            const float* a0 = &g_agg[(size_t)n0c * F];
            const float* a1 = &g_agg[(size_t)(n0c + 1) * F];
            const float* x0 = &xin[(size_t)n0c * F];
            const float* x1 = &xin[(size_t)(n0c + 1) * F];
            sMp[pr * F + j]  = pack2(a0[j],  a1[j]);
            sMp[pr * F + jB] = pack2(a0[jB], a1[jB]);
            sHp[pr * F + j]  = pack2(x0[j],  x1[j]);
            sHp[pr * F + jB] = pack2(x0[jB], x1[jB]);
        }
        __syncthreads();
        // Stage 1: sage = mean@Wl + x@Wr + bl, relu.  k4 iterations (4 k / iter)
        ull accA[8], accB[8];
        #pragma unroll
        for (int p = 0; p < 8; p++) { accA[p] = dup2(blA); accB[p] = dup2(blB); }
        for (int k4 = 0; k4 < F / 4; k4++) {
            float4 wlAv = *(const float4*)&sWlT[j  * F + 4 * k4];
            float4 wlBv = *(const float4*)&sWlT[jB * F + 4 * k4];
            float4 wrAv = *(const float4*)&sWrT[j  * F + 4 * k4];
            float4 wrBv = *(const float4*)&sWrT[jB * F + 4 * k4];
            ull wlA0 = dup2(wlAv.x), wlA1 = dup2(wlAv.y),
                wlA2 = dup2(wlAv.z), wlA3 = dup2(wlAv.w);
            ull wlB0 = dup2(wlBv.x), wlB1 = dup2(wlBv.y),
                wlB2 = dup2(wlBv.z), wlB3 = dup2(wlBv.w);
            ull wrA0 = dup2(wrAv.x), wrA1 = dup2(wrAv.y),
                wrA2 = dup2(wrAv.z), wrA3 = dup2(wrAv.w);
            ull wrB0 = dup2(wrBv.x), wrB1 = dup2(wrBv.y),
                wrB2 = dup2(wrBv.z), wrB3 = dup2(wrBv.w);
            #pragma unroll
            for (int p = 0; p < 8; p++) {
                int pr = g * 8 + p;
                ulonglong2 m0 = mp2[pr * (F / 2) + 2 * k4];
                ulonglong2 m1 = mp2[pr * (F / 2) + 2 * k4 + 1];
                ulonglong2 h0 = hp2[pr * (F / 2) + 2 * k4];
                ulonglong2 h1 = hp2[pr * (F / 2) + 2 * k4 + 1];
                accA[p] = ffma2(m0.x, wlA0, accA[p]);
                accA[p] = ffma2(m0.y, wlA1, accA[p]);
                accA[p] = ffma2(m1.x, wlA2, accA[p]);
                accA[p] = ffma2(m1.y, wlA3, accA[p]);
                accA[p] = ffma2(h0.x, wrA0, accA[p]);
                accA[p] = ffma2(h0.y, wrA1, accA[p]);
                accA[p] = ffma2(h1.x, wrA2, accA[p]);
                accA[p] = ffma2(h1.y, wrA3, accA[p]);
                accB[p] = ffma2(m0.x, wlB0, accB[p]);
                accB[p] = ffma2(m0.y, wlB1, accB[p]);
                accB[p] = ffma2(m1.x, wlB2, accB[p]);
                accB[p] = ffma2(m1.y, wlB3, accB[p]);
                accB[p] = ffma2(h0.x, wrB0, accB[p]);
                accB[p] = ffma2(h0.y, wrB1, accB[p]);
                accB[p] = ffma2(h1.x, wrB2, accB[p]);
                accB[p] = ffma2(h1.y, wrB3, accB[p]);
            }
        }
        __syncthreads();   // stage-1 reads of sMp complete before overwrite
        #pragma unroll
        for (int p = 0; p < 8; p++) {
            int pr = g * 8 + p;
            float2 tA = unpack2(accA[p]);
            float2 tB = unpack2(accB[p]);
            sMp[pr * F + j]  = pack2(fmaxf(tA.x, 0.f), fmaxf(tA.y, 0.f));
            sMp[pr * F + jB] = pack2(fmaxf(tB.x, 0.f), fmaxf(tB.y, 0.f));
        }
        __syncthreads();
        // Stage 2: @W2 + b2   (T lives in sMp)
        ull a2A[8], a2B[8];
        #pragma unroll
        for (int p = 0; p < 8; p++) { a2A[p] = dup2(b2A); a2B[p] = dup2(b2B); }
        for (int k4 = 0; k4 < F / 4; k4++) {
            float4 wAv = *(const float4*)&sW2T[j  * F + 4 * k4];
            float4 wBv = *(const float4*)&sW2T[jB * F + 4 * k4];
            ull wA0 = dup2(wAv.x), wA1 = dup2(wAv.y),
                wA2 = dup2(wAv.z), wA3 = dup2(wAv.w);
            ull wB0 = dup2(wBv.x), wB1 = dup2(wBv.y),
                wB2 = dup2(wBv.z), wB3 = dup2(wBv.w);
            #pragma unroll
            for (int p = 0; p < 8; p++) {
                int pr = g * 8 + p;
                ulonglong2 t0 = mp2[pr * (F / 2) + 2 * k4];
                ulonglong2 t1 = mp2[pr * (F / 2) + 2 * k4 + 1];
                a2A[p] = ffma2(t0.x, wA0, a2A[p]);
                a2A[p] = ffma2(t0.y, wA1, a2A[p]);
                a2A[p] = ffma2(t1.x, wA2, a2A[p]);
                a2A[p] = ffma2(t1.y, wA3, a2A[p]);
                a2B[p] = ffma2(t0.x, wB0, a2B[p]);
                a2B[p] = ffma2(t0.y, wB1, a2B[p]);
                a2B[p] = ffma2(t1.x, wB2, a2B[p]);
                a2B[p] = ffma2(t1.y, wB3, a2B[p]);
            }
        }
        #pragma unroll
        for (int p = 0; p < 8; p++) {
            int n0 = base16 + 2 * p;
            if (n0 < NN) {
                float2 vA = unpack2(a2A[p]);
                float2 vB = unpack2(a2B[p]);
                if (RELU2) {
                    vA.x = fmaxf(vA.x, 0.f); vA.y = fmaxf(vA.y, 0.f);
                    vB.x = fmaxf(vB.x, 0.f); vB.y = fmaxf(vB.y, 0.f);
                }
                out[(size_t)n0 * F + j]        = vA.x;
                out[(size_t)(n0 + 1) * F + j]  = vA.y;
                out[(size_t)n0 * F + jB]       = vB.x;
                out[(size_t)(n0 + 1) * F + jB] = vB.y;
            }
        }
    }
}

#define FUSED_SMEM (112 * 1024)

extern "C" void kernel_launch(void* const* d_in, const int* in_sizes, int n_in,
                              void* d_out, int out_size) {
    const float* h   = (const float*)d_in[0];
    const int*   ei  = (const int*)d_in[1];
    const float* w1l = (const float*)d_in[2];
    const float* b1l = (const float*)d_in[3];
    const float* w1r = (const float*)d_in[4];
    const float* wl1 = (const float*)d_in[5];
    const float* bl1 = (const float*)d_in[6];
    const float* w2l = (const float*)d_in[7];
    const float* b2l = (const float*)d_in[8];
    const float* w2r = (const float*)d_in[9];
    const float* wl2 = (const float*)d_in[10];
    const float* bl2 = (const float*)d_in[11];
    float* out = (float*)d_out;

    int E = in_sizes[1] / 2;
    const int* src = ei;
    const int* dst = ei + E;

    void *p_agg = nullptr, *p_x2 = nullptr;
    cudaGetSymbolAddress(&p_agg, g_agg);
    cudaGetSymbolAddress(&p_x2, g_x2);
    float* agg = (float*)p_agg;
    float* x2  = (float*)p_x2;

    static bool attr_set = false;
    if (!attr_set) {
        cudaFuncSetAttribute(fused_layer<true>,
                             cudaFuncAttributeMaxDynamicSharedMemorySize, FUSED_SMEM);
        cudaFuncSetAttribute(fused_layer<false>,
                             cudaFuncAttributeMaxDynamicSharedMemorySize, FUSED_SMEM);
        attr_set = true;
    }

    int eb = (E + 255) / 256;
    dim3 nb(32, 8);

    // Bucket CSR: 2 launches
    zero_deg_kernel<<<(NN + 255) / 256, 256>>>();
    fill_kernel<<<eb, 256>>>(src, dst, E);

    // Layer 1  (4th launch = fused<true> -> profiled by ncu)
    agg_kernel<<<(NN * 16 + 255) / 256, 256>>>((const float4*)h, (float4*)agg);
    fused_layer<true><<<296, nb, FUSED_SMEM>>>(h, w1l, b1l, w1r, wl1, bl1, x2);
    // Layer 2
    agg_kernel<<<(NN * 16 + 255) / 256, 256>>>((const float4*)x2, (float4*)agg);
    fused_layer<false><<<296, nb, FUSED_SMEM>>>(x2, w2l, b2l, w2r, wl2, bl2, out);
}

// round 16
// speedup vs baseline: 1.5078x; 1.5078x over previous
#include <cuda_runtime.h>

#define NN 100000
#define F  64
#define CAP 64                                 // slots per node (P(deg>=64) ~ 1e-20)
#define NCH3 ((NN + 127) / 128)                // 782 chunks of 128 nodes

typedef unsigned long long ull;

// Scratch (allocation-free: __device__ globals)
__device__ __align__(16) float g_agg[(size_t)NN * F];
__device__ __align__(16) float g_x2[(size_t)NN * F];
__device__ int g_deg[NN];
__device__ __align__(16) int g_slot[(size_t)NN * CAP];   // 25.6 MB bucket rows

__device__ __forceinline__ ull ffma2(ull a, ull b, ull c) {
    ull d;
    asm("fma.rn.f32x2 %0, %1, %2, %3;" : "=l"(d) : "l"(a), "l"(b), "l"(c));
    return d;
}
__device__ __forceinline__ ull dup2(float x) {
    ull d;
    asm("mov.b64 %0, {%1, %1};" : "=l"(d) : "f"(x));
    return d;
}
__device__ __forceinline__ ull pack2(float lo, float hi) {
    ull d;
    asm("mov.b64 %0, {%1, %2};" : "=l"(d) : "f"(lo), "f"(hi));
    return d;
}
__device__ __forceinline__ float2 unpack2(ull v) {
    float2 r;
    asm("mov.b64 {%0, %1}, %2;" : "=f"(r.x), "=f"(r.y) : "l"(v));
    return r;
}

__global__ void zero_deg_kernel() {
    int i = blockIdx.x * blockDim.x + threadIdx.x;
    if (i < NN) g_deg[i] = 0;
}

// Single-pass bucket fill: the fill IS the histogram.
__global__ void fill_kernel(const int* __restrict__ src,
                            const int* __restrict__ dst, int E) {
    int e = blockIdx.x * blockDim.x + threadIdx.x;
    if (e >= E) return;
    int d = __ldg(&dst[e]);
    int s = __ldg(&src[e]);
    if ((unsigned)d >= NN || (unsigned)s >= NN) return;
    int pos = atomicAdd(&g_deg[d], 1);
    if (pos < CAP) g_slot[(size_t)d * CAP + pos] = s;
}

// Bucket mean aggregation: 16 threads/node, float4 slices, int4 index loads.
__global__ void agg_kernel(const float4* __restrict__ x4,
                           float4* __restrict__ out4) {
    int t = blockIdx.x * blockDim.x + threadIdx.x;
    int node = t >> 4;
    int sub = t & 15;
    if (node >= NN) return;
    int degt = g_deg[node];
    int deg = min(degt, CAP);
    const int4* idx4 = reinterpret_cast<const int4*>(&g_slot[(size_t)node * CAP]);
    float4 a = make_float4(0.f, 0.f, 0.f, 0.f);
    float4 b = make_float4(0.f, 0.f, 0.f, 0.f);
    int i = 0;
    for (; i + 4 <= deg; i += 4) {
        int4 q = __ldg(&idx4[i >> 2]);
        float4 v0 = __ldg(&x4[(size_t)q.x * 16 + sub]);
        float4 v1 = __ldg(&x4[(size_t)q.y * 16 + sub]);
        float4 v2 = __ldg(&x4[(size_t)q.z * 16 + sub]);
        float4 v3 = __ldg(&x4[(size_t)q.w * 16 + sub]);
        a.x += v0.x + v1.x; a.y += v0.y + v1.y;
        a.z += v0.z + v1.z; a.w += v0.w + v1.w;
        b.x += v2.x + v3.x; b.y += v2.y + v3.y;
        b.z += v2.z + v3.z; b.w += v2.w + v3.w;
    }
    for (; i < deg; i++) {
        int s0 = g_slot[(size_t)node * CAP + i];
        float4 v0 = __ldg(&x4[(size_t)s0 * 16 + sub]);
        a.x += v0.x; a.y += v0.y; a.z += v0.z; a.w += v0.w;
    }
    float inv = 1.0f / (float)max(degt, 1);
    out4[(size_t)node * 16 + sub] =
        make_float4((a.x + b.x) * inv, (a.y + b.y) * inv,
                    (a.z + b.z) * inv, (a.w + b.w) * inv);
}

// Fused layer, f32x2 FMA. 32 j-lanes x 8 groups; each thread computes
// features j and j+32 for 8 node-pairs -> node broadcasts amortized 2x.
// Chunk = 128 nodes. smem: 48KB weights ([k][j], conflict-free) + 32KB M
// (reused for T) + 32KB H.   (R13-proven configuration.)
template <bool RELU2>
__global__ void __launch_bounds__(256, 2)
fused_layer(const float* __restrict__ xin,
            const float* __restrict__ Wl,
            const float* __restrict__ bl,
            const float* __restrict__ Wr,
            const float* __restrict__ W2,
            const float* __restrict__ b2,
            float* __restrict__ out) {
    extern __shared__ char smraw[];
    float* sWl = (float*)smraw;            // 16KB
    float* sWr = sWl + F * F;              // 16KB
    float* sW2 = sWr + F * F;              // 16KB
    ull* sMp = (ull*)(sW2 + F * F);        // 64 pairs x 64 = 32KB (reused for T)
    ull* sHp = sMp + 64 * F;               // 32KB   (total 112KB)

    int j = threadIdx.x;                   // 0..31
    int g = threadIdx.y;                   // 0..7
    int jB = j + 32;
    int tid = g * 32 + j;
    for (int i = tid; i < F * F; i += 256) {
        sWl[i] = Wl[i]; sWr[i] = Wr[i]; sW2[i] = W2[i];
    }
    float blA = bl[j],  blB = bl[jB];
    float b2A = b2[j],  b2B = b2[jB];

    const ulonglong2* mp2 = (const ulonglong2*)sMp;
    const ulonglong2* hp2 = (const ulonglong2*)sHp;

    for (int chunk = blockIdx.x; chunk < NCH3; chunk += gridDim.x) {
        __syncthreads();
        int base16 = chunk * 128 + g * 16;
        // Stage 8 pairs per group, both feature halves (clamped for tail)
        #pragma unroll
        for (int q = 0; q < 8; q++) {
            int n0 = base16 + 2 * q;
            int n0c = min(n0, NN - 2);
            int pr = g * 8 + q;
            const float* a0 = &g_agg[(size_t)n0c * F];
            const float* a1 = &g_agg[(size_t)(n0c + 1) * F];
            const float* x0 = &xin[(size_t)n0c * F];
            const float* x1 = &xin[(size_t)(n0c + 1) * F];
            sMp[pr * F + j]  = pack2(a0[j],  a1[j]);
            sMp[pr * F + jB] = pack2(a0[jB], a1[jB]);
            sHp[pr * F + j]  = pack2(x0[j],  x1[j]);
            sHp[pr * F + jB] = pack2(x0[jB], x1[jB]);
        }
        __syncthreads();
        // Stage 1: sage = mean@Wl + x@Wr + bl, relu
        ull accA[8], accB[8];
        #pragma unroll
        for (int p = 0; p < 8; p++) { accA[p] = dup2(blA); accB[p] = dup2(blB); }
        for (int k2 = 0; k2 < F / 2; k2++) {
            int k = 2 * k2;
            ull wl0A = dup2(sWl[k * F + j]);
            ull wl1A = dup2(sWl[(k + 1) * F + j]);
            ull wr0A = dup2(sWr[k * F + j]);
            ull wr1A = dup2(sWr[(k + 1) * F + j]);
            ull wl0B = dup2(sWl[k * F + jB]);
            ull wl1B = dup2(sWl[(k + 1) * F + jB]);
            ull wr0B = dup2(sWr[k * F + jB]);
            ull wr1B = dup2(sWr[(k + 1) * F + jB]);
            #pragma unroll
            for (int p = 0; p < 8; p++) {
                ulonglong2 m = mp2[(g * 8 + p) * (F / 2) + k2];
                ulonglong2 h = hp2[(g * 8 + p) * (F / 2) + k2];
                accA[p] = ffma2(m.x, wl0A, accA[p]);
                accA[p] = ffma2(m.y, wl1A, accA[p]);
                accA[p] = ffma2(h.x, wr0A, accA[p]);
                accA[p] = ffma2(h.y, wr1A, accA[p]);
                accB[p] = ffma2(m.x, wl0B, accB[p]);
                accB[p] = ffma2(m.y, wl1B, accB[p]);
                accB[p] = ffma2(h.x, wr0B, accB[p]);
                accB[p] = ffma2(h.y, wr1B, accB[p]);
            }
        }
        __syncthreads();   // stage-1 reads of sMp complete before overwrite
        #pragma unroll
        for (int p = 0; p < 8; p++) {
            int pr = g * 8 + p;
            float2 tA = unpack2(accA[p]);
            float2 tB = unpack2(accB[p]);
            sMp[pr * F + j]  = pack2(fmaxf(tA.x, 0.f), fmaxf(tA.y, 0.f));
            sMp[pr * F + jB] = pack2(fmaxf(tB.x, 0.f), fmaxf(tB.y, 0.f));
        }
        __syncthreads();
        // Stage 2: @W2 + b2   (T lives in sMp)
        ull a2A[8], a2B[8];
        #pragma unroll
        for (int p = 0; p < 8; p++) { a2A[p] = dup2(b2A); a2B[p] = dup2(b2B); }
        for (int k2 = 0; k2 < F / 2; k2++) {
            int k = 2 * k2;
            ull w0A = dup2(sW2[k * F + j]);
            ull w1A = dup2(sW2[(k + 1) * F + j]);
            ull w0B = dup2(sW2[k * F + jB]);
            ull w1B = dup2(sW2[(k + 1) * F + jB]);
            #pragma unroll
            for (int p = 0; p < 8; p++) {
                ulonglong2 t = mp2[(g * 8 + p) * (F / 2) + k2];
                a2A[p] = ffma2(t.x, w0A, a2A[p]);
                a2A[p] = ffma2(t.y, w1A, a2A[p]);
                a2B[p] = ffma2(t.x, w0B, a2B[p]);
                a2B[p] = ffma2(t.y, w1B, a2B[p]);
            }
        }
        #pragma unroll
        for (int p = 0; p < 8; p++) {
            int n0 = base16 + 2 * p;
            if (n0 < NN) {
                float2 vA = unpack2(a2A[p]);
                float2 vB = unpack2(a2B[p]);
                if (RELU2) {
                    vA.x = fmaxf(vA.x, 0.f); vA.y = fmaxf(vA.y, 0.f);
                    vB.x = fmaxf(vB.x, 0.f); vB.y = fmaxf(vB.y, 0.f);
                }
                out[(size_t)n0 * F + j]        = vA.x;
                out[(size_t)(n0 + 1) * F + j]  = vA.y;
                out[(size_t)n0 * F + jB]       = vB.x;
                out[(size_t)(n0 + 1) * F + jB] = vB.y;
            }
        }
    }
}

#define FUSED_SMEM (112 * 1024)

extern "C" void kernel_launch(void* const* d_in, const int* in_sizes, int n_in,
                              void* d_out, int out_size) {
    const float* h   = (const float*)d_in[0];
    const int*   ei  = (const int*)d_in[1];
    const float* w1l = (const float*)d_in[2];
    const float* b1l = (const float*)d_in[3];
    const float* w1r = (const float*)d_in[4];
    const float* wl1 = (const float*)d_in[5];
    const float* bl1 = (const float*)d_in[6];
    const float* w2l = (const float*)d_in[7];
    const float* b2l = (const float*)d_in[8];
    const float* w2r = (const float*)d_in[9];
    const float* wl2 = (const float*)d_in[10];
    const float* bl2 = (const float*)d_in[11];
    float* out = (float*)d_out;

    int E = in_sizes[1] / 2;
    const int* src = ei;
    const int* dst = ei + E;

    void *p_agg = nullptr, *p_x2 = nullptr;
    cudaGetSymbolAddress(&p_agg, g_agg);
    cudaGetSymbolAddress(&p_x2, g_x2);
    float* agg = (float*)p_agg;
    float* x2  = (float*)p_x2;

    static bool attr_set = false;
    if (!attr_set) {
        cudaFuncSetAttribute(fused_layer<true>,
                             cudaFuncAttributeMaxDynamicSharedMemorySize, FUSED_SMEM);
        cudaFuncSetAttribute(fused_layer<false>,
                             cudaFuncAttributeMaxDynamicSharedMemorySize, FUSED_SMEM);
        attr_set = true;
    }

    int eb = (E + 255) / 256;
    dim3 nb(32, 8);

    // Bucket CSR: 2 launches
    zero_deg_kernel<<<(NN + 255) / 256, 256>>>();
    fill_kernel<<<eb, 256>>>(src, dst, E);

    // Layer 1  (4th launch = fused<true> -> profiled by ncu)
    agg_kernel<<<(NN * 16 + 255) / 256, 256>>>((const float4*)h, (float4*)agg);
    fused_layer<true><<<296, nb, FUSED_SMEM>>>(h, w1l, b1l, w1r, wl1, bl1, x2);
    // Layer 2
    agg_kernel<<<(NN * 16 + 255) / 256, 256>>>((const float4*)x2, (float4*)agg);
    fused_layer<false><<<296, nb, FUSED_SMEM>>>(x2, w2l, b2l, w2r, wl2, bl2, out);
}